// round 12
// baseline (speedup 1.0000x reference)
#include <cuda_runtime.h>
#include <cuda_fp16.h>
#include <cstdint>

// SoftSplit: unfold(K=3,S=1,P=1) + Linear(576->96), fp16 implicit GEMM
// (mma.sync.m16n8k16 + ldmatrix), fp32 accumulate.
// R11: register double-buffered LDSM pipeline + split A staging halves.
//   x : (8, 64, 128, 128) f32   W : (96, 576) f32   b : (96,)   out: (8,16384,96) f32

#define B_    8
#define C1    64
#define C2    96
#define HH    128
#define WW    128
#define KTOT  576
#define NSLICE 9
#define KSL   64
#define AROW  272                 // bytes per k-row of A tile (256 data + 16 pad)
#define ATILE (KSL * AROW)        // 17408
#define BTILE 12288

typedef unsigned short u16;
typedef unsigned int   u32;

#define A0_OFF   0
#define A1_OFF   ATILE
#define B0_OFF   (2 * ATILE)              // 34816
#define B1_OFF   (2 * ATILE + BTILE)      // 47104
#define BIAS_OFF (2 * ATILE + 2 * BTILE)  // 59392
#define SMEM_BYTES (BIAS_OFF + 384)       // 59776

// per-slice SW128-swizzled [n][k] fp16 W slabs (12288 B each)
__device__ u16 g_Wh[NSLICE * C2 * KSL];

__device__ __forceinline__ u32 smem_u32(const void* p) {
    u32 a;
    asm("{ .reg .u64 t; cvta.to.shared.u64 t, %1; cvt.u32.u64 %0, t; }"
        : "=r"(a) : "l"(p));
    return a;
}

#define LDSM_X4(r, a)                                                          \
    asm volatile("ldmatrix.sync.aligned.m8n8.x4.shared.b16 {%0,%1,%2,%3}, [%4];" \
        : "=r"((r)[0]), "=r"((r)[1]), "=r"((r)[2]), "=r"((r)[3]) : "r"(a))

#define LDSM_X4_T(r, a)                                                        \
    asm volatile("ldmatrix.sync.aligned.m8n8.x4.trans.shared.b16 {%0,%1,%2,%3}, [%4];" \
        : "=r"((r)[0]), "=r"((r)[1]), "=r"((r)[2]), "=r"((r)[3]) : "r"(a))

#define MMA16816(d, a, b0, b1)                                                 \
    asm volatile("mma.sync.aligned.m16n8k16.row.col.f32.f16.f16.f32 "          \
        "{%0,%1,%2,%3}, {%4,%5,%6,%7}, {%8,%9}, {%0,%1,%2,%3};"                \
        : "+f"((d)[0]), "+f"((d)[1]), "+f"((d)[2]), "+f"((d)[3])               \
        : "r"((a)[0]), "r"((a)[1]), "r"((a)[2]), "r"((a)[3]), "r"(b0), "r"(b1))

#define CVT_F16X2(d, v0, v1) \
    asm("cvt.rn.f16x2.f32 %0, %1, %2;" : "=r"(d) : "f"(v1), "f"(v0))

#define CP_ASYNC16(dst, src) \
    asm volatile("cp.async.cg.shared.global [%0], [%1], 16;" :: "r"(dst), "l"(src))
#define CP_COMMIT()  asm volatile("cp.async.commit_group;" ::: "memory")
#define CP_WAIT0()   asm volatile("cp.async.wait_group 0;" ::: "memory")

#define STS64(a, p0, p1) \
    asm volatile("st.shared.v2.b32 [%0], {%1, %2};" :: "r"(a), "r"(p0), "r"(p1))

// ---------------- prologue: swizzle W to fp16 slabs ----------------
__global__ void pack_w_kernel(const float* __restrict__ W) {
    int i = blockIdx.x * 256 + threadIdx.x;          // NSLICE*C2*KSL = 55296
    if (i < NSLICE * C2 * KSL) {
        int s  = i / (C2 * KSL);
        int r  = i - s * (C2 * KSL);
        int n  = r / KSL;
        int kk = r - n * KSL;
        float v = W[n * KTOT + s * KSL + kk];
        u32 off = (u32)(n * 128 + kk * 2);
        u32 sw  = off ^ ((off >> 3) & 0x70);
        g_Wh[(size_t)s * 6144 + (sw >> 1)] = __half_as_ushort(__float2half_rn(v));
    }
}

// ---------------- main kernel ----------------
__global__ __launch_bounds__(256, 2)
void softsplit_hmma_kernel(const float* __restrict__ x,
                           const float* __restrict__ bias,
                           float* __restrict__ out) {
    extern __shared__ char smem[];
    const u32 Su = smem_u32(smem);
    float* bs = (float*)(smem + BIAS_OFF);

    const int bb   = blockIdx.x >> 7;
    const int row  = blockIdx.x & 127;
    const int tid  = threadIdx.x;
    const int wid  = tid >> 5;
    const int lane = tid & 31;

    if (tid < C2) bs[tid] = bias[tid];

    // warp tile: m32 x n48.  4 m-groups x 2 n-halves.
    const int mw = (wid & 3) << 5;            // 0,32,64,96
    const int nw = (wid >> 2) * 48;           // 0 or 48
    const int gB = (wid >> 2) * 3;            // B n16-group base (0 or 3)

    const u32 xsw   = (u32)((lane & 7) << 4);
    const u32 bRowO = (u32)((((lane & 7) + ((lane >> 1) & 8))) << 7);
    const u32 bKq   = (u32)((lane & 8) << 1);
    const u32 aOff  = (u32)(((lane & 7) + ((lane & 16) >> 1)) * AROW
                            + ((mw + (lane & 8)) << 1));

    float acc[2][6][4];
#pragma unroll
    for (int a = 0; a < 2; ++a)
#pragma unroll
        for (int j = 0; j < 6; ++j)
#pragma unroll
            for (int q = 0; q < 4; ++q) acc[a][j][q] = 0.f;

    const float* xb = x + ((size_t)bb * C1 * HH * WW) + (lane << 2);

    // staging registers (one half-slice: 2 k-pairs)
    float4 q0[2], q1[2];
    u32 sa0[2];
    int kjv[2];

    // pipelined LDSM register buffers
    u32 aP0[2][4], aP1[2][4], bP[2][4];

    // ---- stage A half (its IT0, IT0+1) of slice ss into regs ----
#define STAGE_A_H(ss, Abuf, IT0)                                               \
    {                                                                          \
        _Pragma("unroll")                                                      \
        for (int ii = 0; ii < 2; ++ii) {                                       \
            const int it = (IT0) + ii;                                         \
            const int klocal = 2 * (it * 8 + wid);                             \
            const int k0 = (ss) * KSL + klocal;                                \
            const int c0 = k0 / 9, t0 = k0 - 9 * c0;                           \
            const int ki0 = t0 / 3, kj0 = t0 - 3 * ki0;                        \
            const int gr0 = row - 1 + ki0;                                     \
            const float4 z = {0.f, 0.f, 0.f, 0.f};                             \
            q0[ii] = ((unsigned)gr0 < (unsigned)HH)                            \
                ? *(const float4*)(xb + (((size_t)c0 * HH + gr0) << 7)) : z;   \
            if (kj0 == 2) {                                                    \
                const int k1 = k0 + 1;                                         \
                const int c1 = k1 / 9, t1 = k1 - 9 * c1;                       \
                const int ki1 = t1 / 3;                                        \
                const int gr1 = row - 1 + ki1;                                 \
                q1[ii] = ((unsigned)gr1 < (unsigned)HH)                        \
                    ? *(const float4*)(xb + (((size_t)c1 * HH + gr1) << 7)) : z; \
            }                                                                  \
            sa0[ii] = (Abuf) + (u32)(klocal * AROW) + (u32)(lane << 3);        \
            kjv[ii] = kj0;                                                     \
        }                                                                      \
    }

#define FINISH_A_H()                                                           \
    {                                                                          \
        _Pragma("unroll")                                                      \
        for (int ii = 0; ii < 2; ++ii) {                                       \
            const int kj0 = kjv[ii];                                           \
            float w0, w1, w2, w3, u0, u1, u2, u3;                              \
            if (kj0 == 0) {                                                    \
                float eL = __shfl_up_sync(0xffffffffu, q0[ii].w, 1);           \
                if (lane == 0) eL = 0.f;                                       \
                w0 = eL;        w1 = q0[ii].x; w2 = q0[ii].y; w3 = q0[ii].z;   \
                u0 = q0[ii].x;  u1 = q0[ii].y; u2 = q0[ii].z; u3 = q0[ii].w;   \
            } else if (kj0 == 1) {                                             \
                float eR = __shfl_down_sync(0xffffffffu, q0[ii].x, 1);         \
                if (lane == 31) eR = 0.f;                                      \
                w0 = q0[ii].x;  w1 = q0[ii].y; w2 = q0[ii].z; w3 = q0[ii].w;   \
                u0 = q0[ii].y;  u1 = q0[ii].z; u2 = q0[ii].w; u3 = eR;         \
            } else {                                                           \
                float eR = __shfl_down_sync(0xffffffffu, q0[ii].x, 1);         \
                if (lane == 31) eR = 0.f;                                      \
                float eL = __shfl_up_sync(0xffffffffu, q1[ii].w, 1);           \
                if (lane == 0) eL = 0.f;                                       \
                w0 = q0[ii].y;  w1 = q0[ii].z; w2 = q0[ii].w; w3 = eR;         \
                u0 = eL;        u1 = q1[ii].x; u2 = q1[ii].y; u3 = q1[ii].z;   \
            }                                                                  \
            u32 pa, pb;                                                        \
            CVT_F16X2(pa, w0, w1); CVT_F16X2(pb, w2, w3);                      \
            STS64(sa0[ii], pa, pb);                                            \
            CVT_F16X2(pa, u0, u1); CVT_F16X2(pb, u2, u3);                      \
            STS64(sa0[ii] + AROW, pa, pb);                                     \
        }                                                                      \
    }

#define STAGE_B(ss, Bbuf)                                                      \
    {                                                                          \
        const char* src = (const char*)g_Wh + (size_t)(ss) * BTILE + (tid << 4); \
        _Pragma("unroll")                                                      \
        for (int i = 0; i < 3; ++i)                                            \
            CP_ASYNC16((Bbuf) + (u32)(tid << 4) + (u32)(i * 4096),             \
                       src + i * 4096);                                        \
    }

    // B address helper
#define B_ADDR(Bb, ks, g) \
    ((Bb) + (u32)(((gB) + (g)) << 11) + bRowO + (((u32)((ks) * 32) + bKq) ^ xsw))

    // one k-chunk of MMAs with double-buffered LDSM prefetch
#define COMPUTE_KS(Ab, Bb, ks)                                                 \
    {                                                                          \
        const int cur = (ks) & 1, nxt = cur ^ 1;                               \
        _Pragma("unroll")                                                      \
        for (int g = 0; g < 3; ++g) {                                          \
            const int bc = (((ks) * 3) + g) & 1, bn = bc ^ 1;                  \
            if (g < 2) {                                                       \
                LDSM_X4(bP[bn], B_ADDR(Bb, ks, g + 1));                        \
            } else if ((ks) < 3) {                                             \
                LDSM_X4(bP[bn], B_ADDR(Bb, (ks) + 1, 0));                      \
                LDSM_X4_T(aP0[nxt], (Ab) + aOff + (u32)(((ks) + 1) * 16 * AROW)); \
                LDSM_X4_T(aP1[nxt], (Ab) + aOff + (u32)(((ks) + 1) * 16 * AROW) + 32); \
            }                                                                  \
            MMA16816(acc[0][2 * g],     aP0[cur], bP[bc][0], bP[bc][1]);       \
            MMA16816(acc[0][2 * g + 1], aP0[cur], bP[bc][2], bP[bc][3]);       \
            MMA16816(acc[1][2 * g],     aP1[cur], bP[bc][0], bP[bc][1]);       \
            MMA16816(acc[1][2 * g + 1], aP1[cur], bP[bc][2], bP[bc][3]);       \
        }                                                                      \
    }

#define PRELOAD_SLICE(Ab, Bb)                                                  \
    {                                                                          \
        LDSM_X4(bP[0], B_ADDR(Bb, 0, 0));                                      \
        LDSM_X4_T(aP0[0], (Ab) + aOff);                                        \
        LDSM_X4_T(aP1[0], (Ab) + aOff + 32);                                   \
    }

    // ---- prologue: slice 0 ----
    STAGE_B(0, Su + B0_OFF);
    CP_COMMIT();
    STAGE_A_H(0, Su + A0_OFF, 0);
    FINISH_A_H();
    STAGE_A_H(0, Su + A0_OFF, 2);
    FINISH_A_H();
    CP_WAIT0();
    __syncthreads();

    for (int s = 0; s < NSLICE; ++s) {
        const int p = s & 1;
        const u32 Ab = Su + (p ? A1_OFF : A0_OFF);
        const u32 Bb = Su + (p ? B1_OFF : B0_OFF);
        const u32 An = Su + (p ? A0_OFF : A1_OFF);
        const u32 Bn = Su + (p ? B0_OFF : B1_OFF);
        const bool more = (s + 1 < NSLICE);

        if (more) {
            STAGE_B(s + 1, Bn);
            CP_COMMIT();
            STAGE_A_H(s + 1, An, 0);
        }

        PRELOAD_SLICE(Ab, Bb);
        COMPUTE_KS(Ab, Bb, 0);
        COMPUTE_KS(Ab, Bb, 1);

        if (more) {
            FINISH_A_H();
            STAGE_A_H(s + 1, An, 2);
        }

        COMPUTE_KS(Ab, Bb, 2);
        COMPUTE_KS(Ab, Bb, 3);

        if (more) {
            FINISH_A_H();
            CP_WAIT0();
        }
        __syncthreads();
    }

    // ---- epilogue: D + bias -> out (8,16384,96) ----
    const int r  = lane >> 2;
    const int cb = (lane & 3) << 1;
#pragma unroll
    for (int a = 0; a < 2; ++a) {
        const int mrow = mw + a * 16 + r;
        float* oro = out + ((size_t)(bb * (HH * WW) + (row << 7) + mrow)) * C2 + nw;
        float* or8 = oro + 8 * C2;
#pragma unroll
        for (int j = 0; j < 6; ++j) {
            const int n = (j << 3) + cb;
            float2 v0, v1;
            v0.x = acc[a][j][0] + bs[nw + n];     v0.y = acc[a][j][1] + bs[nw + n + 1];
            v1.x = acc[a][j][2] + bs[nw + n];     v1.y = acc[a][j][3] + bs[nw + n + 1];
            *(float2*)(oro + n) = v0;
            *(float2*)(or8 + n) = v1;
        }
    }
}

extern "C" void kernel_launch(void* const* d_in, const int* in_sizes, int n_in,
                              void* d_out, int out_size) {
    const float* x = (const float*)d_in[0];   // (8,64,128,128)
    const float* W = (const float*)d_in[1];   // (96,576)
    const float* b = (const float*)d_in[2];   // (96,)
    float* out = (float*)d_out;               // (8,16384,96)

    cudaFuncSetAttribute(softsplit_hmma_kernel,
                         cudaFuncAttributeMaxDynamicSharedMemorySize, SMEM_BYTES);

    pack_w_kernel<<<(NSLICE * C2 * KSL + 255) / 256, 256>>>(W);
    softsplit_hmma_kernel<<<B_ * HH, 256, SMEM_BYTES>>>(x, b, out);
}

// round 16
// speedup vs baseline: 1.0259x; 1.0259x over previous
#include <cuda_runtime.h>
#include <cuda_fp16.h>
#include <cstdint>

// SoftSplit: unfold(K=3,S=1,P=1) + Linear(576->96), fp16 implicit GEMM
// (mma.sync.m16n8k16 + ldmatrix), fp32 accumulate.
// R12: KSL=96 (6 slices, fewer barriers), padded-linear B layout (208B rows).
//   x : (8, 64, 128, 128) f32   W : (96, 576) f32   b : (96,)   out: (8,16384,96) f32

#define B_    8
#define C1    64
#define C2    96
#define HH    128
#define WW    128
#define KTOT  576
#define NSLICE 6
#define KSL   96
#define AROW  272                 // bytes per k-row of A tile (256 data + 16 pad)
#define ATILE (KSL * AROW)        // 26112
#define BROW  208                 // bytes per n-row of B tile (192 data + 16 pad)
#define BTILE 20480               // 96*208 = 19968, padded to 20480 (1280 x 16B)

typedef unsigned short u16;
typedef unsigned int   u32;

#define A0_OFF   0
#define A1_OFF   ATILE                    // 26112
#define B0_OFF   (2 * ATILE)              // 52224
#define B1_OFF   (2 * ATILE + BTILE)      // 72704
#define BIAS_OFF (2 * ATILE + 2 * BTILE)  // 93184
#define SMEM_BYTES (BIAS_OFF + 384)       // 93568  (x2 CTA = 187136 <= 227KB)

// per-slice padded-linear [n][96k] fp16 W slabs (20480 B each, 10240 u16)
__device__ u16 g_Wh[NSLICE * 10240];

__device__ __forceinline__ u32 smem_u32(const void* p) {
    u32 a;
    asm("{ .reg .u64 t; cvta.to.shared.u64 t, %1; cvt.u32.u64 %0, t; }"
        : "=r"(a) : "l"(p));
    return a;
}

#define LDSM_X4(r, a)                                                          \
    asm volatile("ldmatrix.sync.aligned.m8n8.x4.shared.b16 {%0,%1,%2,%3}, [%4];" \
        : "=r"((r)[0]), "=r"((r)[1]), "=r"((r)[2]), "=r"((r)[3]) : "r"(a))

#define LDSM_X4_T(r, a)                                                        \
    asm volatile("ldmatrix.sync.aligned.m8n8.x4.trans.shared.b16 {%0,%1,%2,%3}, [%4];" \
        : "=r"((r)[0]), "=r"((r)[1]), "=r"((r)[2]), "=r"((r)[3]) : "r"(a))

#define MMA16816(d, a, b0, b1)                                                 \
    asm volatile("mma.sync.aligned.m16n8k16.row.col.f32.f16.f16.f32 "          \
        "{%0,%1,%2,%3}, {%4,%5,%6,%7}, {%8,%9}, {%0,%1,%2,%3};"                \
        : "+f"((d)[0]), "+f"((d)[1]), "+f"((d)[2]), "+f"((d)[3])               \
        : "r"((a)[0]), "r"((a)[1]), "r"((a)[2]), "r"((a)[3]), "r"(b0), "r"(b1))

#define CVT_F16X2(d, v0, v1) \
    asm("cvt.rn.f16x2.f32 %0, %1, %2;" : "=r"(d) : "f"(v1), "f"(v0))

#define CP_ASYNC16(dst, src) \
    asm volatile("cp.async.cg.shared.global [%0], [%1], 16;" :: "r"(dst), "l"(src))
#define CP_COMMIT()  asm volatile("cp.async.commit_group;" ::: "memory")
#define CP_WAIT0()   asm volatile("cp.async.wait_group 0;" ::: "memory")

#define STS64(a, p0, p1) \
    asm volatile("st.shared.v2.b32 [%0], {%1, %2};" :: "r"(a), "r"(p0), "r"(p1))

// ---------------- prologue: pack W to padded-linear fp16 slabs ----------------
__global__ void pack_w_kernel(const float* __restrict__ W) {
    int i = blockIdx.x * 256 + threadIdx.x;          // NSLICE*C2*KSL = 55296
    if (i < NSLICE * C2 * KSL) {
        int s  = i / (C2 * KSL);
        int r  = i - s * (C2 * KSL);
        int n  = r / KSL;
        int kk = r - n * KSL;
        float v = W[n * KTOT + s * KSL + kk];
        g_Wh[s * 10240 + n * 104 + kk] = __half_as_ushort(__float2half_rn(v));
    }
}

// ---------------- main kernel ----------------
__global__ __launch_bounds__(256, 2)
void softsplit_hmma_kernel(const float* __restrict__ x,
                           const float* __restrict__ bias,
                           float* __restrict__ out) {
    extern __shared__ char smem[];
    const u32 Su = smem_u32(smem);
    float* bs = (float*)(smem + BIAS_OFF);

    const int bb   = blockIdx.x >> 7;
    const int row  = blockIdx.x & 127;
    const int tid  = threadIdx.x;
    const int wid  = tid >> 5;
    const int lane = tid & 31;

    if (tid < C2) bs[tid] = bias[tid];

    // warp tile: m32 x n48.  4 m-groups x 2 n-halves.
    const int mw = (wid & 3) << 5;            // 0,32,64,96
    const int nw = (wid >> 2) * 48;           // 0 or 48
    const int gB = (wid >> 2) * 3;            // B n16-group base (0 or 3)

    // A-side trans-ldmatrix base (272-B k-rows)
    const u32 aOff = (u32)(((lane & 7) + ((lane & 16) >> 1)) * AROW
                           + ((mw + (lane & 8)) << 1));
    // B-side ldmatrix base (208-B n-rows, linear)
    const u32 bBase = (u32)((gB * 16 + (lane & 7) + ((lane >> 1) & 8)) * BROW
                            + ((lane & 8) << 1));

    float acc[2][6][4];
#pragma unroll
    for (int a = 0; a < 2; ++a)
#pragma unroll
        for (int j = 0; j < 6; ++j)
#pragma unroll
            for (int q = 0; q < 4; ++q) acc[a][j][q] = 0.f;

    const float* xb = x + ((size_t)bb * C1 * HH * WW) + (lane << 2);

    // staging registers (one stage: 2 k-pairs)
    float4 q0[2], q1[2];
    u32 sa0[2];
    int kjv[2];

    // ---- stage A (2 k-pairs, stage H of 3) of slice ss into regs ----
#define STAGE_A_H(ss, Abuf, H)                                                 \
    {                                                                          \
        _Pragma("unroll")                                                      \
        for (int ii = 0; ii < 2; ++ii) {                                       \
            const int klocal = 2 * ((H) * 16 + ii * 8 + wid);                  \
            const int k0 = (ss) * KSL + klocal;                                \
            const int c0 = k0 / 9, t0 = k0 - 9 * c0;                           \
            const int ki0 = t0 / 3, kj0 = t0 - 3 * ki0;                        \
            const int gr0 = row - 1 + ki0;                                     \
            const float4 z = {0.f, 0.f, 0.f, 0.f};                             \
            q0[ii] = ((unsigned)gr0 < (unsigned)HH)                            \
                ? *(const float4*)(xb + (((size_t)c0 * HH + gr0) << 7)) : z;   \
            if (kj0 == 2) {                                                    \
                const int k1 = k0 + 1;                                         \
                const int c1 = k1 / 9, t1 = k1 - 9 * c1;                       \
                const int ki1 = t1 / 3;                                        \
                const int gr1 = row - 1 + ki1;                                 \
                q1[ii] = ((unsigned)gr1 < (unsigned)HH)                        \
                    ? *(const float4*)(xb + (((size_t)c1 * HH + gr1) << 7)) : z; \
            }                                                                  \
            sa0[ii] = (Abuf) + (u32)(klocal * AROW) + (u32)(lane << 3);        \
            kjv[ii] = kj0;                                                     \
        }                                                                      \
    }

#define FINISH_A_H()                                                           \
    {                                                                          \
        _Pragma("unroll")                                                      \
        for (int ii = 0; ii < 2; ++ii) {                                       \
            const int kj0 = kjv[ii];                                           \
            float w0, w1, w2, w3, u0, u1, u2, u3;                              \
            if (kj0 == 0) {                                                    \
                float eL = __shfl_up_sync(0xffffffffu, q0[ii].w, 1);           \
                if (lane == 0) eL = 0.f;                                       \
                w0 = eL;        w1 = q0[ii].x; w2 = q0[ii].y; w3 = q0[ii].z;   \
                u0 = q0[ii].x;  u1 = q0[ii].y; u2 = q0[ii].z; u3 = q0[ii].w;   \
            } else if (kj0 == 1) {                                             \
                float eR = __shfl_down_sync(0xffffffffu, q0[ii].x, 1);         \
                if (lane == 31) eR = 0.f;                                      \
                w0 = q0[ii].x;  w1 = q0[ii].y; w2 = q0[ii].z; w3 = q0[ii].w;   \
                u0 = q0[ii].y;  u1 = q0[ii].z; u2 = q0[ii].w; u3 = eR;         \
            } else {                                                           \
                float eR = __shfl_down_sync(0xffffffffu, q0[ii].x, 1);         \
                if (lane == 31) eR = 0.f;                                      \
                float eL = __shfl_up_sync(0xffffffffu, q1[ii].w, 1);           \
                if (lane == 0) eL = 0.f;                                       \
                w0 = q0[ii].y;  w1 = q0[ii].z; w2 = q0[ii].w; w3 = eR;         \
                u0 = eL;        u1 = q1[ii].x; u2 = q1[ii].y; u3 = q1[ii].z;   \
            }                                                                  \
            u32 pa, pb;                                                        \
            CVT_F16X2(pa, w0, w1); CVT_F16X2(pb, w2, w3);                      \
            STS64(sa0[ii], pa, pb);                                            \
            CVT_F16X2(pa, u0, u1); CVT_F16X2(pb, u2, u3);                      \
            STS64(sa0[ii] + AROW, pa, pb);                                     \
        }                                                                      \
    }

#define STAGE_B(ss, Bbuf)                                                      \
    {                                                                          \
        const char* src = (const char*)g_Wh + (size_t)(ss) * BTILE + (tid << 4); \
        _Pragma("unroll")                                                      \
        for (int i = 0; i < 5; ++i)                                            \
            CP_ASYNC16((Bbuf) + (u32)(tid << 4) + (u32)(i * 4096),             \
                       src + i * 4096);                                        \
    }

    // ---- one k16-chunk of MMAs (ks in 0..5) ----
#define COMPUTE_KS(Ab, Bb, ks)                                                 \
    {                                                                          \
        u32 aF0[4], aF1[4];                                                    \
        const u32 ka = (Ab) + aOff + (u32)((ks) * 16 * AROW);                  \
        LDSM_X4_T(aF0, ka);                                                    \
        LDSM_X4_T(aF1, ka + 32);                                               \
        _Pragma("unroll")                                                      \
        for (int g = 0; g < 3; ++g) {                                          \
            u32 bF[4];                                                         \
            LDSM_X4(bF, (Bb) + bBase + (u32)(g * 16 * BROW) + (u32)((ks) * 32)); \
            MMA16816(acc[0][2 * g],     aF0, bF[0], bF[1]);                    \
            MMA16816(acc[0][2 * g + 1], aF0, bF[2], bF[3]);                    \
            MMA16816(acc[1][2 * g],     aF1, bF[0], bF[1]);                    \
            MMA16816(acc[1][2 * g + 1], aF1, bF[2], bF[3]);                    \
        }                                                                      \
    }

    // ---- prologue: slice 0 ----
    STAGE_B(0, Su + B0_OFF);
    CP_COMMIT();
    STAGE_A_H(0, Su + A0_OFF, 0); FINISH_A_H();
    STAGE_A_H(0, Su + A0_OFF, 1); FINISH_A_H();
    STAGE_A_H(0, Su + A0_OFF, 2); FINISH_A_H();
    CP_WAIT0();
    __syncthreads();

    for (int s = 0; s < NSLICE; ++s) {
        const int p = s & 1;
        const u32 Ab = Su + (p ? A1_OFF : A0_OFF);
        const u32 Bb = Su + (p ? B1_OFF : B0_OFF);
        const u32 An = Su + (p ? A0_OFF : A1_OFF);
        const u32 Bn = Su + (p ? B0_OFF : B1_OFF);
        const bool more = (s + 1 < NSLICE);

        if (more) {
            STAGE_B(s + 1, Bn);
            CP_COMMIT();
            STAGE_A_H(s + 1, An, 0);
        }

        COMPUTE_KS(Ab, Bb, 0);
        COMPUTE_KS(Ab, Bb, 1);

        if (more) {
            FINISH_A_H();
            STAGE_A_H(s + 1, An, 1);
        }

        COMPUTE_KS(Ab, Bb, 2);
        COMPUTE_KS(Ab, Bb, 3);

        if (more) {
            FINISH_A_H();
            STAGE_A_H(s + 1, An, 2);
        }

        COMPUTE_KS(Ab, Bb, 4);
        COMPUTE_KS(Ab, Bb, 5);

        if (more) {
            FINISH_A_H();
            CP_WAIT0();
        }
        __syncthreads();
    }

    // ---- epilogue: D + bias -> out (8,16384,96) ----
    const int r  = lane >> 2;
    const int cb = (lane & 3) << 1;
#pragma unroll
    for (int a = 0; a < 2; ++a) {
        const int mrow = mw + a * 16 + r;
        float* oro = out + ((size_t)(bb * (HH * WW) + (row << 7) + mrow)) * C2 + nw;
        float* or8 = oro + 8 * C2;
#pragma unroll
        for (int j = 0; j < 6; ++j) {
            const int n = (j << 3) + cb;
            float2 v0, v1;
            v0.x = acc[a][j][0] + bs[nw + n];     v0.y = acc[a][j][1] + bs[nw + n + 1];
            v1.x = acc[a][j][2] + bs[nw + n];     v1.y = acc[a][j][3] + bs[nw + n + 1];
            *(float2*)(oro + n) = v0;
            *(float2*)(or8 + n) = v1;
        }
    }
}

extern "C" void kernel_launch(void* const* d_in, const int* in_sizes, int n_in,
                              void* d_out, int out_size) {
    const float* x = (const float*)d_in[0];   // (8,64,128,128)
    const float* W = (const float*)d_in[1];   // (96,576)
    const float* b = (const float*)d_in[2];   // (96,)
    float* out = (float*)d_out;               // (8,16384,96)

    cudaFuncSetAttribute(softsplit_hmma_kernel,
                         cudaFuncAttributeMaxDynamicSharedMemorySize, SMEM_BYTES);

    pack_w_kernel<<<(NSLICE * C2 * KSL + 255) / 256, 256>>>(W);
    softsplit_hmma_kernel<<<B_ * HH, 256, SMEM_BYTES>>>(x, b, out);
}